// round 9
// baseline (speedup 1.0000x reference)
#include <cuda_runtime.h>
#include <math.h>

#define D   4096
#define H   64
#define S   64
#define EPSF 1e-5f

// Scratch (allocation-free rule: __device__ globals)
__device__ float g_mix[4 * D];    // [r, k, v, g] mixed input vectors
__device__ float g_rkvg[4 * D];   // [r, k, v, g] matvec results
__device__ float g_y[D];          // gated, normalized wkv -> input to Wo
__device__ float g_part[2 * D];   // split-K partials for Wo matvec

// ---------------------------------------------------------------------------
// Kernel 1: LayerNorm(x) + 4 token-mixes. Single block, 256 threads.
// Triggers PDL completion at entry so matvec4 can prefetch weights meanwhile.
// ---------------------------------------------------------------------------
__global__ __launch_bounds__(256) void ln_mix_kernel(
    const float* __restrict__ x, const float* __restrict__ state1,
    const float* __restrict__ tmr, const float* __restrict__ tmk,
    const float* __restrict__ tmv, const float* __restrict__ tmg,
    const float* __restrict__ ln1_w, const float* __restrict__ ln1_b,
    float* __restrict__ state1_out)
{
    cudaTriggerProgrammaticLaunchCompletion();
    int tid = threadIdx.x;
    float4 xv[4];
    float s = 0.f, sq = 0.f;
#pragma unroll
    for (int k = 0; k < 4; k++) {
        xv[k] = ((const float4*)x)[tid + k * 256];
        s  += xv[k].x + xv[k].y + xv[k].z + xv[k].w;
        sq += xv[k].x * xv[k].x + xv[k].y * xv[k].y
            + xv[k].z * xv[k].z + xv[k].w * xv[k].w;
    }
    __shared__ float sa[8], sb[8];
#pragma unroll
    for (int o = 16; o; o >>= 1) {
        s  += __shfl_xor_sync(0xffffffffu, s, o);
        sq += __shfl_xor_sync(0xffffffffu, sq, o);
    }
    int w = tid >> 5, l = tid & 31;
    if (l == 0) { sa[w] = s; sb[w] = sq; }
    __syncthreads();
    __shared__ float s_mean, s_rstd;
    if (tid == 0) {
        float ts = 0.f, tq = 0.f;
#pragma unroll
        for (int i = 0; i < 8; i++) { ts += sa[i]; tq += sb[i]; }
        float m   = ts * (1.0f / D);
        float var = tq * (1.0f / D) - m * m;
        s_mean = m;
        s_rstd = rsqrtf(var + EPSF);
    }
    __syncthreads();
    float m = s_mean, rstd = s_rstd;

#pragma unroll
    for (int k = 0; k < 4; k++) {
        int idx = tid + k * 256;
        float4 w4 = ((const float4*)ln1_w)[idx];
        float4 b4 = ((const float4*)ln1_b)[idx];
        float4 st = ((const float4*)state1)[idx];
        float4 xx;
        xx.x = (xv[k].x - m) * rstd * w4.x + b4.x;
        xx.y = (xv[k].y - m) * rstd * w4.y + b4.y;
        xx.z = (xv[k].z - m) * rstd * w4.z + b4.z;
        xx.w = (xv[k].w - m) * rstd * w4.w + b4.w;
        ((float4*)state1_out)[idx] = xx;

        const float* tms[4] = {tmr, tmk, tmv, tmg};
#pragma unroll
        for (int mi = 0; mi < 4; mi++) {
            float4 t = ((const float4*)tms[mi])[idx];
            float4 o;
            o.x = st.x * (1.f - t.x) + xx.x * t.x;
            o.y = st.y * (1.f - t.y) + xx.y * t.y;
            o.z = st.z * (1.f - t.z) + xx.z * t.z;
            o.w = st.w * (1.f - t.w) + xx.w * t.w;
            ((float4*)(g_mix + mi * D))[idx] = o;
        }
    }
}

// ---------------------------------------------------------------------------
// Kernel 2: fused 4x matvec (Wr,Wk,Wv,Wg). One row per block, 8 warps/row.
// grid = (4096, 4), block = 256. Weight prefetch before grid-dep sync.
// ---------------------------------------------------------------------------
__global__ __launch_bounds__(256) void matvec4_kernel(
    const float* __restrict__ Wr, const float* __restrict__ Wk,
    const float* __restrict__ Wv, const float* __restrict__ Wg)
{
    cudaTriggerProgrammaticLaunchCompletion();
    int m = blockIdx.y;
    const float* W = (m == 0) ? Wr : (m == 1) ? Wk : (m == 2) ? Wv : Wg;

    int warp = threadIdx.x >> 5, lane = threadIdx.x & 31;
    const float* Wp = W + (size_t)blockIdx.x * D + warp * 512 + lane * 4;

    // Weight loads are independent of the previous kernel -> issue first.
    float4 w0 = __ldcs((const float4*)(Wp + 0 * 128));
    float4 w1 = __ldcs((const float4*)(Wp + 1 * 128));
    float4 w2 = __ldcs((const float4*)(Wp + 2 * 128));
    float4 w3 = __ldcs((const float4*)(Wp + 3 * 128));

    cudaGridDependencySynchronize();   // wait for ln_mix writes to g_mix

    const float* xp = g_mix + m * D + warp * 512 + lane * 4;
    float4 x0 = *(const float4*)(xp + 0 * 128);
    float4 x1 = *(const float4*)(xp + 1 * 128);
    float4 x2 = *(const float4*)(xp + 2 * 128);
    float4 x3 = *(const float4*)(xp + 3 * 128);

    float a0 = w0.x * x0.x + w0.y * x0.y + w0.z * x0.z + w0.w * x0.w;
    float a1 = w1.x * x1.x + w1.y * x1.y + w1.z * x1.z + w1.w * x1.w;
    float a2 = w2.x * x2.x + w2.y * x2.y + w2.z * x2.z + w2.w * x2.w;
    float a3 = w3.x * x3.x + w3.y * x3.y + w3.z * x3.z + w3.w * x3.w;
    float acc = (a0 + a1) + (a2 + a3);
#pragma unroll
    for (int o = 16; o; o >>= 1) acc += __shfl_xor_sync(0xffffffffu, acc, o);

    __shared__ float part[8];
    if (lane == 0) part[warp] = acc;
    __syncthreads();
    if (threadIdx.x == 0) {
        float r = ((part[0] + part[1]) + (part[2] + part[3]))
                + ((part[4] + part[5]) + (part[6] + part[7]));
        g_rkvg[m * D + blockIdx.x] = r;
    }
}

// ---------------------------------------------------------------------------
// Kernel 3: per-head WKV + state2 update + InstanceNorm + SiLU gate.
// grid = 64 heads, block = 256. float4 over j; state2 prefetch before sync.
// Thread t: jg = t&15 (float4 group of j), ig = t>>4 (4 i-rows each).
// ---------------------------------------------------------------------------
__global__ __launch_bounds__(256) void wkv_kernel(
    const float* __restrict__ state2, const float* __restrict__ time_decay,
    const float* __restrict__ time_first, const float* __restrict__ lnx_w,
    const float* __restrict__ lnx_b, float* __restrict__ state2_out)
{
    cudaTriggerProgrammaticLaunchCompletion();
    int h = blockIdx.x, t = threadIdx.x;
    int jg = t & 15, ig = t >> 4;

    const float4* S2  = (const float4*)(state2 + (size_t)h * S * S);
    float4*       S2o = (float4*)(state2_out + (size_t)h * S * S);

    // state2 tiles are independent of matvec4 -> prefetch.
    float4 s2v[4];
#pragma unroll
    for (int di = 0; di < 4; di++)
        s2v[di] = S2[(ig * 4 + di) * 16 + jg];

    cudaGridDependencySynchronize();   // wait for g_rkvg

    __shared__ float sk[S], sr[S], stf[S], sdec[S];
    __shared__ float pw[16][S];
    __shared__ float sw[S];
    if (t < S) {
        sr[t]   = g_rkvg[0 * D + h * S + t];
        sk[t]   = g_rkvg[1 * D + h * S + t];
        stf[t]  = time_first[h * S + t];
        sdec[t] = time_decay[h * S + t];
    }
    float4 vj = ((const float4*)(g_rkvg + 2 * D + h * S))[jg];
    __syncthreads();

    float4 acc = make_float4(0.f, 0.f, 0.f, 0.f);
#pragma unroll
    for (int di = 0; di < 4; di++) {
        int i = ig * 4 + di;
        float ki = sk[i], ri = sr[i], tfi = stf[i], dci = sdec[i];
        float4 s2 = s2v[di];
        float4 kv = make_float4(ki * vj.x, ki * vj.y, ki * vj.z, ki * vj.w);
        float4 so;
        so.x = kv.x + s2.x * dci; so.y = kv.y + s2.y * dci;
        so.z = kv.z + s2.z * dci; so.w = kv.w + s2.w * dci;
        S2o[i * 16 + jg] = so;
        acc.x += ri * (kv.x * tfi + s2.x);
        acc.y += ri * (kv.y * tfi + s2.y);
        acc.z += ri * (kv.z * tfi + s2.z);
        acc.w += ri * (kv.w * tfi + s2.w);
    }
    ((float4*)&pw[ig][0])[jg] = acc;
    __syncthreads();

    if (t < S) {
        float wsum = 0.f;
#pragma unroll
        for (int g2 = 0; g2 < 16; g2++) wsum += pw[g2][t];
        sw[t] = wsum;
    }
    __syncthreads();
    if (t < S) {
        float s = 0.f, sq = 0.f;
#pragma unroll
        for (int i = 0; i < S; i++) { float u = sw[i]; s += u; sq += u * u; }
        float mu  = s * (1.0f / S);
        float var = sq * (1.0f / S) - mu * mu;
        float xn  = (sw[t] - mu) * rsqrtf(var + EPSF);

        float g    = g_rkvg[3 * D + h * S + t];
        float gate = g / (1.f + expf(-g));   // SiLU
        g_y[h * S + t] = (xn * lnx_w[h * S + t] + lnx_b[h * S + t]) * gate;
    }
}

// ---------------------------------------------------------------------------
// Kernel 4: split-K partial of Wo @ y. grid = (4096 rows, 2 halves), 8 warps.
// Warp covers 256 elems (2x LDG.128). Weight prefetch before sync.
// ---------------------------------------------------------------------------
__global__ __launch_bounds__(256) void matvec_out_part(
    const float* __restrict__ Wo)
{
    cudaTriggerProgrammaticLaunchCompletion();
    int warp = threadIdx.x >> 5, lane = threadIdx.x & 31;
    int row  = blockIdx.x, half = blockIdx.y;
    int off  = half * 2048 + warp * 256 + lane * 4;
    const float* Wp = Wo + (size_t)row * D + off;

    float4 w0 = __ldcs((const float4*)(Wp + 0 * 128));
    float4 w1 = __ldcs((const float4*)(Wp + 1 * 128));

    cudaGridDependencySynchronize();   // wait for g_y

    const float* yp = g_y + off;
    float4 y0 = *(const float4*)(yp + 0 * 128);
    float4 y1 = *(const float4*)(yp + 1 * 128);

    float a0 = w0.x * y0.x + w0.y * y0.y + w0.z * y0.z + w0.w * y0.w;
    float a1 = w1.x * y1.x + w1.y * y1.y + w1.z * y1.z + w1.w * y1.w;
    float acc = a0 + a1;
#pragma unroll
    for (int o = 16; o; o >>= 1) acc += __shfl_xor_sync(0xffffffffu, acc, o);

    __shared__ float part[8];
    if (lane == 0) part[warp] = acc;
    __syncthreads();
    if (threadIdx.x == 0) {
        float r = ((part[0] + part[1]) + (part[2] + part[3]))
                + ((part[4] + part[5]) + (part[6] + part[7]));
        g_part[half * D + row] = r;
    }
}

// ---------------------------------------------------------------------------
// Kernel 5: out = x + partial0 + partial1. grid = 16, block = 256.
// ---------------------------------------------------------------------------
__global__ __launch_bounds__(256) void combine_kernel(
    const float* __restrict__ x, float* __restrict__ out)
{
    int i = blockIdx.x * 256 + threadIdx.x;
    float xv = x[i];                       // input, independent
    cudaGridDependencySynchronize();       // wait for g_part
    out[i] = xv + (g_part[i] + g_part[D + i]);
}

// ---------------------------------------------------------------------------
extern "C" void kernel_launch(void* const* d_in, const int* in_sizes, int n_in,
                              void* d_out, int out_size)
{
    const float* x      = (const float*)d_in[0];
    const float* state1 = (const float*)d_in[1];
    const float* state2 = (const float*)d_in[2];
    const float* tmk    = (const float*)d_in[3];
    const float* tmv    = (const float*)d_in[4];
    const float* tmr    = (const float*)d_in[5];
    const float* tmg    = (const float*)d_in[6];
    const float* tdec   = (const float*)d_in[7];
    const float* tfir   = (const float*)d_in[8];
    const float* Wr     = (const float*)d_in[9];
    const float* Wk     = (const float*)d_in[10];
    const float* Wv     = (const float*)d_in[11];
    const float* Wg     = (const float*)d_in[12];
    const float* Wo     = (const float*)d_in[13];
    const float* ln1w   = (const float*)d_in[14];
    const float* ln1b   = (const float*)d_in[15];
    const float* lnxw   = (const float*)d_in[16];
    const float* lnxb   = (const float*)d_in[17];

    float* out        = (float*)d_out;         // [0, D)
    float* state1_out = out + D;               // [D, 2D)
    float* state2_out = out + 2 * D;           // [2D, 2D + H*S*S)

    ln_mix_kernel<<<1, 256>>>(x, state1, tmr, tmk, tmv, tmg, ln1w, ln1b,
                              state1_out);

    cudaLaunchAttribute at[1];
    at[0].id = cudaLaunchAttributeProgrammaticStreamSerialization;
    at[0].val.programmaticStreamSerializationAllowed = 1;
    cudaLaunchConfig_t cfg = {};
    cfg.blockDim = dim3(256, 1, 1);
    cfg.dynamicSmemBytes = 0;
    cfg.stream = 0;
    cfg.attrs = at;
    cfg.numAttrs = 1;

    cfg.gridDim = dim3(4096, 4, 1);
    cudaLaunchKernelEx(&cfg, matvec4_kernel, Wr, Wk, Wv, Wg);

    cfg.gridDim = dim3(64, 1, 1);
    cudaLaunchKernelEx(&cfg, wkv_kernel, state2, tdec, tfir, lnxw, lnxb,
                       state2_out);

    cfg.gridDim = dim3(4096, 2, 1);
    cudaLaunchKernelEx(&cfg, matvec_out_part, Wo);

    cfg.gridDim = dim3(16, 1, 1);
    cudaLaunchKernelEx(&cfg, combine_kernel, x, out);
}